// round 13
// baseline (speedup 1.0000x reference)
#include <cuda_runtime.h>
#include <cuda_bf16.h>
#include <math.h>

// ---------------------------------------------------------------------------
#define BB 512
#define VV 6890
#define NJ 24
#define NBETA 10
#define NP 207
#define NJO 19
#define VC (VV*3)              // 20670
#define VCP 20736              // padded cols (216*96)
#define KTOT 217
#define KPAD 224               // 14*16
#define JNT_OFF  (BB*VC)
#define ROT_OFF  (JNT_OFF + BB*NJO*3)

typedef unsigned long long u64;

__device__ __forceinline__ u64 ffma2(u64 a, u64 b, u64 c) {
    u64 d;
    asm("fma.rn.f32x2 %0, %1, %2, %3;" : "=l"(d) : "l"(a), "l"(b), "l"(c));
    return d;
}
__device__ __forceinline__ u64 add2(u64 a, u64 b) {
    u64 d;
    asm("add.rn.f32x2 %0, %1, %2;" : "=l"(d) : "l"(a), "l"(b));
    return d;
}
__device__ __forceinline__ u64 pack2(float lo, float hi) {
    u64 d;
    asm("mov.b64 %0, {%1, %2};" : "=l"(d) : "f"(lo), "f"(hi));
    return d;
}
__device__ __forceinline__ float2 unpack2(u64 v) {
    float2 f;
    asm("mov.b64 {%0, %1}, %2;" : "=f"(f.x), "=f"(f.y) : "l"(v));
    return f;
}
__device__ __forceinline__ void cp_async16(unsigned saddr, const void* gaddr) {
    asm volatile("cp.async.ca.shared.global [%0], [%1], 16;"
                 :: "r"(saddr), "l"(gaddr));
}
__device__ __forceinline__ void cp_commit() {
    asm volatile("cp.async.commit_group;");
}
template<int N>
__device__ __forceinline__ void cp_wait() {
    asm volatile("cp.async.wait_group %0;" :: "n"(N));
}
__device__ __forceinline__ float tf32r(float x) {
    unsigned u;
    asm("cvt.rna.tf32.f32 %0, %1;" : "=r"(u) : "f"(x));
    return __uint_as_float(u);
}
__device__ __forceinline__ unsigned tf32u(float x) {
    unsigned u;
    asm("cvt.rna.tf32.f32 %0, %1;" : "=r"(u) : "f"(x));
    return u;
}
__device__ __forceinline__ void mma_tf32(float* c, const unsigned* a, unsigned b0, unsigned b1) {
    asm("mma.sync.aligned.m16n8k8.row.col.f32.tf32.tf32.f32 "
        "{%0,%1,%2,%3},{%4,%5,%6,%7},{%8,%9},{%0,%1,%2,%3};"
        : "+f"(c[0]), "+f"(c[1]), "+f"(c[2]), "+f"(c[3])
        : "r"(a[0]), "r"(a[1]), "r"(a[2]), "r"(a[3]), "r"(b0), "r"(b1));
}

// ---------------------------------------------------------------------------
__device__ float    g_pfT[KPAD * BB];
__device__ unsigned g_pd[(size_t)KPAD * VCP];
__device__ float    g_A[BB * NJ * 12];
__device__ float    g_jmp[NJ * 8 * 33];
__device__ float    g_jm[NJ * 33];
__device__ float    g_jpart[BB * 14 * 57];

// ---------------------------------------------------------------------------
// Kernel R: pre-round [posedirs;shapes] -> g_pd (tf32 bits, padded)
// ---------------------------------------------------------------------------
__global__ void __launch_bounds__(256) k_round(const float* __restrict__ pd,
                                               const float* __restrict__ sh)
{
    int k  = blockIdx.y;
    int c4 = (blockIdx.x * 256 + threadIdx.x) * 4;
    if (c4 >= VCP) return;
    uint4 o;
    #pragma unroll
    for (int e = 0; e < 4; ++e) {
        int c = c4 + e;
        float f = 0.f;
        if (c < VC) {
            if (k < NP)        f = pd[(size_t)k*VC + c];
            else if (k < KTOT) f = sh[(size_t)(k-NP)*VC + c];
        }
        (&o.x)[e] = tf32u(f);
    }
    *reinterpret_cast<uint4*>(&g_pd[(size_t)k*VCP + c4]) = o;
}

// ---------------------------------------------------------------------------
// Kernel 0: batch-independent precompute for rest joints
// ---------------------------------------------------------------------------
__global__ void __launch_bounds__(128) k_jm(const float* __restrict__ vt,
                                            const float* __restrict__ shp,
                                            const float* __restrict__ sr)
{
    int j = blockIdx.x, part = blockIdx.y;
    int vs = part * 862;
    int ve = vs + 862; if (ve > VV) ve = VV;

    float acc[33];
    #pragma unroll
    for (int i = 0; i < 33; ++i) acc[i] = 0.f;

    for (int v = vs + threadIdx.x; v < ve; v += 128) {
        float w = sr[v * NJ + j];
        acc[0] += vt[v*3+0] * w;
        acc[1] += vt[v*3+1] * w;
        acc[2] += vt[v*3+2] * w;
        #pragma unroll
        for (int k = 0; k < NBETA; ++k) {
            const float* s = shp + k * VC + v * 3;
            acc[3+k*3+0] += s[0] * w;
            acc[3+k*3+1] += s[1] * w;
            acc[3+k*3+2] += s[2] * w;
        }
    }
    #pragma unroll
    for (int m = 16; m > 0; m >>= 1)
        #pragma unroll
        for (int i = 0; i < 33; ++i)
            acc[i] += __shfl_xor_sync(0xffffffffu, acc[i], m);

    __shared__ float s[4][33];
    int wid = threadIdx.x >> 5, lane = threadIdx.x & 31;
    if (lane == 0)
        #pragma unroll
        for (int i = 0; i < 33; ++i) s[wid][i] = acc[i];
    __syncthreads();
    if (threadIdx.x < 33) {
        float t = s[0][threadIdx.x] + s[1][threadIdx.x] + s[2][threadIdx.x] + s[3][threadIdx.x];
        g_jmp[(j*8 + part)*33 + threadIdx.x] = t;
    }
}

__global__ void k_jmred()
{
    int i = blockIdx.x * blockDim.x + threadIdx.x;
    if (i < NJ * 33) {
        int jj = i / 33, r = i % 33;
        float t = 0.f;
        #pragma unroll
        for (int p = 0; p < 8; ++p) t += g_jmp[(jj*8 + p)*33 + r];
        g_jm[i] = t;
    }
}

// ---------------------------------------------------------------------------
// Kernel 1: fused Rodrigues + kinematic chain. 32 batches per block.
// betas staged in smem (kills 240 redundant gmem reads per thread).
// ---------------------------------------------------------------------------
__global__ void __launch_bounds__(96) k_rotchain(const float* __restrict__ inp,
                                                 float* __restrict__ out)
{
    const int PAR[NJ] = {0,0,0,0,1,2,3,4,5,6,7,8,9,9,9,12,13,14,16,17,18,19,20,21};
    __shared__ float s_jm[NJ * 33];
    __shared__ float sJ[32][NJ*3];
    __shared__ float sR[32][NJ*9];
    __shared__ float s_beta[32*NBETA];

    const int tid = threadIdx.x;
    const int b0 = blockIdx.x * 32;

    for (int i = tid; i < NJ*33; i += 96) s_jm[i] = g_jm[i];
    for (int i = tid; i < 32*NBETA; i += 96) {
        int bl = i / NBETA, k = i % NBETA;
        s_beta[i] = inp[(b0+bl)*82 + 72 + k];
    }

    for (int i = tid; i < 32*NJ; i += 96) {
        int bl = i / NJ, j = i % NJ;
        int b = b0 + bl;
        float rx = inp[b*82 + j*3 + 0];
        float ry = inp[b*82 + j*3 + 1];
        float rz = inp[b*82 + j*3 + 2];
        float ax = rx + 1e-8f, ay = ry + 1e-8f, az = rz + 1e-8f;
        float ang = sqrtf(ax*ax + ay*ay + az*az);
        float inv = 1.0f / ang;
        float nx = rx * inv, ny = ry * inv, nz = rz * inv;
        float c = cosf(ang), sn = sinf(ang), ic = 1.0f - c;
        float R[9];
        R[0] = c + ic*nx*nx;     R[1] = ic*nx*ny - sn*nz; R[2] = ic*nx*nz + sn*ny;
        R[3] = ic*ny*nx + sn*nz; R[4] = c + ic*ny*ny;     R[5] = ic*ny*nz - sn*nx;
        R[6] = ic*nz*nx - sn*ny; R[7] = ic*nz*ny + sn*nx; R[8] = c + ic*nz*nz;

        float* ro = out + ROT_OFF + (size_t)b*(NJ*9) + j*9;
        #pragma unroll
        for (int e = 0; e < 9; ++e) { ro[e] = R[e]; sR[bl][j*9+e] = R[e]; }

        if (j > 0) {
            int base = (j-1) * 9;
            #pragma unroll
            for (int e = 0; e < 9; ++e)
                g_pfT[(base + e) * BB + b] = tf32r(R[e] - ((e==0||e==4||e==8) ? 1.0f : 0.0f));
        }
    }
    __syncthreads();

    for (int i = tid; i < 32*NJ*3; i += 96) {
        int bl = i / 72, rem = i % 72;
        int j = rem / 3, c = rem % 3;
        float t = s_jm[j*33 + c];
        #pragma unroll
        for (int k = 0; k < NBETA; ++k)
            t = fmaf(s_beta[bl*NBETA + k], s_jm[j*33 + 3 + k*3 + c], t);
        sJ[bl][j*3 + c] = t;
    }
    __syncthreads();

    const int bl = tid / 3;
    const int r  = tid % 3;
    const int b  = b0 + bl;
    const float* Rb = sR[bl];

    float row[NJ][3];
    float tw[NJ];
    row[0][0] = Rb[r*3+0]; row[0][1] = Rb[r*3+1]; row[0][2] = Rb[r*3+2];
    tw[0] = sJ[bl][r];

    #pragma unroll
    for (int j = 1; j < NJ; ++j) {
        const int p = PAR[j];
        float t0 = sJ[bl][j*3+0] - sJ[bl][p*3+0];
        float t1 = sJ[bl][j*3+1] - sJ[bl][p*3+1];
        float t2 = sJ[bl][j*3+2] - sJ[bl][p*3+2];
        float p0 = row[p][0], p1 = row[p][1], p2 = row[p][2];
        row[j][0] = p0*Rb[j*9+0] + p1*Rb[j*9+3] + p2*Rb[j*9+6];
        row[j][1] = p0*Rb[j*9+1] + p1*Rb[j*9+4] + p2*Rb[j*9+7];
        row[j][2] = p0*Rb[j*9+2] + p1*Rb[j*9+5] + p2*Rb[j*9+8];
        tw[j] = p0*t0 + p1*t1 + p2*t2 + tw[p];
    }

    float* Ao = g_A + (size_t)b * (NJ*12);
    #pragma unroll
    for (int j = 0; j < NJ; ++j) {
        float tp = tw[j] - (row[j][0]*sJ[bl][j*3+0] + row[j][1]*sJ[bl][j*3+1] + row[j][2]*sJ[bl][j*3+2]);
        float4 st = make_float4(row[j][0], row[j][1], row[j][2], tp);
        *reinterpret_cast<float4*>(&Ao[j*12 + r*4]) = st;
    }

    if (r == 0) {
        #pragma unroll
        for (int k = 0; k < NBETA; ++k) g_pfT[(NP + k)*BB + b] = tf32r(s_beta[bl*NBETA + k]);
        #pragma unroll
        for (int k = KTOT; k < KPAD; ++k) g_pfT[k*BB + b] = 0.0f;
    }
}

// ---------------------------------------------------------------------------
// Kernel 2: blendshape GEMM (mma.sync tf32) + LBS skinning epilogue.
// Tile: 128 batches x 96 cols, 256 threads (8 warps, each M=16b x N=96c).
// KS=16 slabs, BOTH operands cp.async double-buffered; 14 kt iterations.
// smem 34.3 KB -> 3 CTAs/SM (launch_bounds 256,3).
// ---------------------------------------------------------------------------
__global__ void __launch_bounds__(256, 3) k_main(const float* __restrict__ lbs,
                                                 const float* __restrict__ vtempl,
                                                 float* __restrict__ out)
{
    __shared__ __align__(16) float smem[8576];
    float* s_d  = smem;            // 2 x 1664 (16 x 104)
    float* s_pf = smem + 3328;     // 2 x 2176 (16 x 136)
    float* s_A  = smem;            // epilogue alias (4608 <= 7680)
    float* s_vp = smem + 4608;     // epilogue alias (1536)
    float* s_w  = smem + 7680;     // [32][25]
    float* s_vt = smem + 8480;     // [96]

    const int b0   = blockIdx.y * 128;
    const int col0 = blockIdx.x * 96;
    const int v0   = blockIdx.x * 32;
    const int tid  = threadIdx.x;
    const int lane = tid & 31;
    const int warp = tid >> 5;        // 16 batches each
    const int g  = lane >> 2;         // 0..7
    const int tg = lane & 3;          // 0..3

    const unsigned sd_base  = (unsigned)__cvta_generic_to_shared(s_d);
    const unsigned spf_base = (unsigned)__cvta_generic_to_shared(s_pf);

    auto load_tiles = [&](int kt, int buf) {
        // d: 16 k-rows x 24 float4
        #pragma unroll
        for (int i = tid; i < 384; i += 256) {
            int k = i / 24, q = i % 24;
            cp_async16(sd_base + (unsigned)(buf*1664 + k*104 + q*4)*4u,
                       g_pd + (size_t)(kt*16 + k)*VCP + col0 + q*4);
        }
        // pf: 16 k-rows x 32 float4 (128 batches)
        #pragma unroll
        for (int i = tid; i < 512; i += 256) {
            int k = i >> 5, q = i & 31;
            cp_async16(spf_base + (unsigned)(buf*2176 + k*136 + q*4)*4u,
                       &g_pfT[(kt*16 + k)*BB + b0 + q*4]);
        }
        cp_commit();
    };

    load_tiles(0, 0);

    float c[12][4];
    #pragma unroll
    for (int i = 0; i < 12; ++i)
        #pragma unroll
        for (int e = 0; e < 4; ++e) c[i][e] = 0.f;

    for (int kt = 0; kt < 14; ++kt) {
        const int buf = kt & 1;
        if (kt < 13) { load_tiles(kt+1, buf ^ 1); cp_wait<1>(); }
        else         { cp_wait<0>(); }
        __syncthreads();

        const float*    pa = s_pf + buf*2176 + tg*136 + warp*16 + g;
        const unsigned* pb = reinterpret_cast<const unsigned*>(s_d + buf*1664) + tg*104 + g;

        #pragma unroll
        for (int ks = 0; ks < 2; ++ks) {
            const float*    pak = pa + ks*1088;   // ks*8*136
            const unsigned* pbk = pb + ks*832;    // ks*8*104
            unsigned a[4];
            a[0] = __float_as_uint(pak[0]);
            a[1] = __float_as_uint(pak[8]);
            a[2] = __float_as_uint(pak[544]);     // +4*136
            a[3] = __float_as_uint(pak[552]);
            #pragma unroll
            for (int nt = 0; nt < 12; ++nt) {
                unsigned bb0 = pbk[nt*8];
                unsigned bb1 = pbk[nt*8 + 416];   // +4*104
                mma_tf32(c[nt], a, bb0, bb1);
            }
        }
        __syncthreads();
    }

    // ---- epilogue: LBS skinning ----
    for (int i = tid; i < 768; i += 256) {
        int vl = i / 24, j = i % 24;
        int v = v0 + vl;
        s_w[vl*25 + j] = (v < VV) ? lbs[(size_t)v*NJ + j] : 0.f;
    }
    if (tid < 96) {
        int cg = col0 + tid;
        s_vt[tid] = (cg < VC) ? vtempl[cg] : 0.f;
    }

    const u64 z2 = pack2(0.f, 0.f);
    const int tv = tid & 15;
    const int tb = tid >> 4;
    const int vg0 = v0 + tv*2;
    const int vg1 = vg0 + 1;

    #pragma unroll
    for (int pass = 0; pass < 8; ++pass) {
        __syncthreads();
        if (warp == pass) {
            #pragma unroll
            for (int nt = 0; nt < 12; ++nt) {
                int colL = nt*8 + tg*2;
                float vt0 = s_vt[colL], vt1 = s_vt[colL+1];
                s_vp[g*96 + colL]        = c[nt][0] + vt0;
                s_vp[g*96 + colL + 1]    = c[nt][1] + vt1;
                s_vp[(g+8)*96 + colL]    = c[nt][2] + vt0;
                s_vp[(g+8)*96 + colL+1]  = c[nt][3] + vt1;
            }
        }
        {
            const float4* gA4 = reinterpret_cast<const float4*>(g_A + (size_t)(b0 + pass*16)*288);
            #pragma unroll
            for (int i = 0; i < 5; ++i) {
                int idx = tid + i*256;
                if (idx < 1152) reinterpret_cast<float4*>(s_A)[idx] = gA4[idx];
            }
        }
        __syncthreads();

        const int b = b0 + pass*16 + tb;
        const ulonglong2* Ar2 = reinterpret_cast<const ulonglong2*>(s_A + tb*288);
        u64 T0[6], T1[6];
        #pragma unroll
        for (int i = 0; i < 6; ++i) { T0[i] = z2; T1[i] = z2; }
        #pragma unroll
        for (int j = 0; j < NJ; ++j) {
            ulonglong2 A01 = Ar2[j*3 + 0];
            ulonglong2 A23 = Ar2[j*3 + 1];
            ulonglong2 A45 = Ar2[j*3 + 2];
            float w0 = s_w[(tv*2 + 0)*25 + j];
            float w1 = s_w[(tv*2 + 1)*25 + j];
            u64 w0d = pack2(w0, w0);
            u64 w1d = pack2(w1, w1);
            T0[0] = ffma2(w0d, A01.x, T0[0]); T0[1] = ffma2(w0d, A01.y, T0[1]);
            T0[2] = ffma2(w0d, A23.x, T0[2]); T0[3] = ffma2(w0d, A23.y, T0[3]);
            T0[4] = ffma2(w0d, A45.x, T0[4]); T0[5] = ffma2(w0d, A45.y, T0[5]);
            T1[0] = ffma2(w1d, A01.x, T1[0]); T1[1] = ffma2(w1d, A01.y, T1[1]);
            T1[2] = ffma2(w1d, A23.x, T1[2]); T1[3] = ffma2(w1d, A23.y, T1[3]);
            T1[4] = ffma2(w1d, A45.x, T1[4]); T1[5] = ffma2(w1d, A45.y, T1[5]);
        }
        if (vg0 < VV) {
            float x = s_vp[tb*96 + tv*6 + 0];
            float y = s_vp[tb*96 + tv*6 + 1];
            float z = s_vp[tb*96 + tv*6 + 2];
            float2 r0 = unpack2(T0[0]), r1 = unpack2(T0[1]);
            float2 r2 = unpack2(T0[2]), r3 = unpack2(T0[3]);
            float2 r4 = unpack2(T0[4]), r5 = unpack2(T0[5]);
            float* o = out + (size_t)b*VC + vg0*3;
            o[0] = r0.x*x + r0.y*y + r1.x*z + r1.y;
            o[1] = r2.x*x + r2.y*y + r3.x*z + r3.y;
            o[2] = r4.x*x + r4.y*y + r5.x*z + r5.y;
        }
        if (vg1 < VV) {
            float x = s_vp[tb*96 + tv*6 + 3];
            float y = s_vp[tb*96 + tv*6 + 4];
            float z = s_vp[tb*96 + tv*6 + 5];
            float2 r0 = unpack2(T1[0]), r1 = unpack2(T1[1]);
            float2 r2 = unpack2(T1[2]), r3 = unpack2(T1[3]);
            float2 r4 = unpack2(T1[4]), r5 = unpack2(T1[5]);
            float* o = out + (size_t)b*VC + vg1*3;
            o[0] = r0.x*x + r0.y*y + r1.x*z + r1.y;
            o[1] = r2.x*x + r2.y*y + r3.x*z + r3.y;
            o[2] = r4.x*x + r4.y*y + r5.x*z + r5.y;
        }
    }
}

// ---------------------------------------------------------------------------
// Kernel 3: joints = vertices @ joint_regressor (deterministic 2-stage).
// jreg j-pairs pre-packed as u64 in smem [jp][512] (conflict-free LDS.64);
// accumulation in FFMA2 (30 per vert vs 57 FFMA).
// ---------------------------------------------------------------------------
__global__ void __launch_bounds__(256) k_jnt_part(const float* __restrict__ outv,
                                                  const float* __restrict__ jreg)
{
    __shared__ u64 s_jp[10 * 512];   // 40 KB
    const int chunk = blockIdx.x;
    const int v0 = chunk * 512;
    for (int i = threadIdx.x; i < 10*512; i += 256) {
        int jp = i >> 9, vl = i & 511;
        int vg = v0 + vl;
        float r0 = 0.f, r1 = 0.f;
        if (vg < VV) {
            r0 = jreg[vg*NJO + 2*jp];
            if (2*jp + 1 < NJO) r1 = jreg[vg*NJO + 2*jp + 1];
        }
        s_jp[jp*512 + vl] = pack2(r0, r1);
    }
    __syncthreads();

    const int bl = threadIdx.x >> 5, lane = threadIdx.x & 31;
    const int b = blockIdx.y * 8 + bl;

    u64 ax[10], ay[10], az[10];
    const u64 z2 = pack2(0.f, 0.f);
    #pragma unroll
    for (int i = 0; i < 10; ++i) { ax[i] = z2; ay[i] = z2; az[i] = z2; }

    #pragma unroll 4
    for (int i = 0; i < 16; ++i) {
        int vl = lane + i*32;
        int vg = v0 + vl;
        if (vg < VV) {
            const float* p = outv + (size_t)b*VC + vg*3;
            float x = p[0], y = p[1], z = p[2];
            u64 xx = pack2(x, x), yy = pack2(y, y), zz = pack2(z, z);
            #pragma unroll
            for (int jp = 0; jp < 10; ++jp) {
                u64 rp = s_jp[jp*512 + vl];
                ax[jp] = ffma2(rp, xx, ax[jp]);
                ay[jp] = ffma2(rp, yy, ay[jp]);
                az[jp] = ffma2(rp, zz, az[jp]);
            }
        }
    }
    #pragma unroll
    for (int m = 16; m > 0; m >>= 1)
        #pragma unroll
        for (int jp = 0; jp < 10; ++jp) {
            ax[jp] = add2(ax[jp], __shfl_xor_sync(0xffffffffu, ax[jp], m));
            ay[jp] = add2(ay[jp], __shfl_xor_sync(0xffffffffu, ay[jp], m));
            az[jp] = add2(az[jp], __shfl_xor_sync(0xffffffffu, az[jp], m));
        }

    if (lane == 0) {
        float* dst = g_jpart + (size_t)(b*14 + chunk)*57;
        #pragma unroll
        for (int jp = 0; jp < 10; ++jp) {
            float2 fx = unpack2(ax[jp]);
            float2 fy = unpack2(ay[jp]);
            float2 fz = unpack2(az[jp]);
            int j0 = 2*jp;
            dst[j0*3+0] = fx.x; dst[j0*3+1] = fy.x; dst[j0*3+2] = fz.x;
            if (j0 + 1 < NJO) {
                dst[(j0+1)*3+0] = fx.y; dst[(j0+1)*3+1] = fy.y; dst[(j0+1)*3+2] = fz.y;
            }
        }
    }
}

__global__ void k_jnt_red(float* __restrict__ out)
{
    int i = blockIdx.x * blockDim.x + threadIdx.x;
    if (i < BB * 57) {
        int b = i / 57, r = i % 57;
        float t = 0.f;
        #pragma unroll
        for (int p = 0; p < 14; ++p) t += g_jpart[(size_t)(b*14 + p)*57 + r];
        out[JNT_OFF + i] = t;
    }
}

// ---------------------------------------------------------------------------
extern "C" void kernel_launch(void* const* d_in, const int* in_sizes, int n_in,
                              void* d_out, int out_size)
{
    const float* inputs   = (const float*)d_in[0];
    const float* v_templ  = (const float*)d_in[1];
    const float* shapes   = (const float*)d_in[2];
    const float* posedirs = (const float*)d_in[3];
    const float* smpl_reg = (const float*)d_in[4];
    const float* lbs_w    = (const float*)d_in[5];
    const float* joint_rg = (const float*)d_in[6];
    float* out = (float*)d_out;

    k_round<<<dim3(21, KPAD), 256>>>(posedirs, shapes);

    k_jm<<<dim3(NJ, 8), 128>>>(v_templ, shapes, smpl_reg);
    k_jmred<<<4, 256>>>();

    k_rotchain<<<16, 96>>>(inputs, out);

    k_main<<<dim3(216, 4), 256>>>(lbs_w, v_templ, out);

    k_jnt_part<<<dim3(14, 64), 256>>>(out, joint_rg);
    k_jnt_red<<<(BB*57 + 255)/256, 256>>>(out);
}

// round 14
// speedup vs baseline: 1.0313x; 1.0313x over previous
#include <cuda_runtime.h>
#include <cuda_bf16.h>
#include <math.h>

// ---------------------------------------------------------------------------
#define BB 512
#define VV 6890
#define NJ 24
#define NBETA 10
#define NP 207
#define NJO 19
#define VC (VV*3)              // 20670
#define VCP 20736              // padded cols (216*96)
#define KTOT 217
#define KPAD 224               // 7*32
#define JNT_OFF  (BB*VC)
#define ROT_OFF  (JNT_OFF + BB*NJO*3)

typedef unsigned long long u64;

__device__ __forceinline__ u64 ffma2(u64 a, u64 b, u64 c) {
    u64 d;
    asm("fma.rn.f32x2 %0, %1, %2, %3;" : "=l"(d) : "l"(a), "l"(b), "l"(c));
    return d;
}
__device__ __forceinline__ u64 add2(u64 a, u64 b) {
    u64 d;
    asm("add.rn.f32x2 %0, %1, %2;" : "=l"(d) : "l"(a), "l"(b));
    return d;
}
__device__ __forceinline__ u64 pack2(float lo, float hi) {
    u64 d;
    asm("mov.b64 %0, {%1, %2};" : "=l"(d) : "f"(lo), "f"(hi));
    return d;
}
__device__ __forceinline__ float2 unpack2(u64 v) {
    float2 f;
    asm("mov.b64 {%0, %1}, %2;" : "=f"(f.x), "=f"(f.y) : "l"(v));
    return f;
}
__device__ __forceinline__ void cp_async16(unsigned saddr, const void* gaddr) {
    asm volatile("cp.async.ca.shared.global [%0], [%1], 16;"
                 :: "r"(saddr), "l"(gaddr));
}
__device__ __forceinline__ void cp_commit() {
    asm volatile("cp.async.commit_group;");
}
template<int N>
__device__ __forceinline__ void cp_wait() {
    asm volatile("cp.async.wait_group %0;" :: "n"(N));
}
__device__ __forceinline__ float tf32r(float x) {
    unsigned u;
    asm("cvt.rna.tf32.f32 %0, %1;" : "=r"(u) : "f"(x));
    return __uint_as_float(u);
}
__device__ __forceinline__ unsigned tf32u(float x) {
    unsigned u;
    asm("cvt.rna.tf32.f32 %0, %1;" : "=r"(u) : "f"(x));
    return u;
}
__device__ __forceinline__ void mma_tf32(float* c, const unsigned* a, unsigned b0, unsigned b1) {
    asm("mma.sync.aligned.m16n8k8.row.col.f32.tf32.tf32.f32 "
        "{%0,%1,%2,%3},{%4,%5,%6,%7},{%8,%9},{%0,%1,%2,%3};"
        : "+f"(c[0]), "+f"(c[1]), "+f"(c[2]), "+f"(c[3])
        : "r"(a[0]), "r"(a[1]), "r"(a[2]), "r"(a[3]), "r"(b0), "r"(b1));
}

// ---------------------------------------------------------------------------
__device__ float    g_pfT[KPAD * BB];
__device__ unsigned g_pd[(size_t)KPAD * VCP];
__device__ float    g_A[BB * NJ * 12];
__device__ float    g_jmp[NJ * 8 * 33];
__device__ float    g_jm[NJ * 33];
__device__ float    g_jpart[BB * 14 * 57];

// ---------------------------------------------------------------------------
// Kernel R: pre-round [posedirs;shapes] -> g_pd (tf32 bits, padded)
// ---------------------------------------------------------------------------
__global__ void __launch_bounds__(256) k_round(const float* __restrict__ pd,
                                               const float* __restrict__ sh)
{
    int k  = blockIdx.y;
    int c4 = (blockIdx.x * 256 + threadIdx.x) * 4;
    if (c4 >= VCP) return;
    uint4 o;
    #pragma unroll
    for (int e = 0; e < 4; ++e) {
        int c = c4 + e;
        float f = 0.f;
        if (c < VC) {
            if (k < NP)        f = pd[(size_t)k*VC + c];
            else if (k < KTOT) f = sh[(size_t)(k-NP)*VC + c];
        }
        (&o.x)[e] = tf32u(f);
    }
    *reinterpret_cast<uint4*>(&g_pd[(size_t)k*VCP + c4]) = o;
}

// ---------------------------------------------------------------------------
// Kernel 0: batch-independent precompute for rest joints
// ---------------------------------------------------------------------------
__global__ void __launch_bounds__(128) k_jm(const float* __restrict__ vt,
                                            const float* __restrict__ shp,
                                            const float* __restrict__ sr)
{
    int j = blockIdx.x, part = blockIdx.y;
    int vs = part * 862;
    int ve = vs + 862; if (ve > VV) ve = VV;

    float acc[33];
    #pragma unroll
    for (int i = 0; i < 33; ++i) acc[i] = 0.f;

    for (int v = vs + threadIdx.x; v < ve; v += 128) {
        float w = sr[v * NJ + j];
        acc[0] += vt[v*3+0] * w;
        acc[1] += vt[v*3+1] * w;
        acc[2] += vt[v*3+2] * w;
        #pragma unroll
        for (int k = 0; k < NBETA; ++k) {
            const float* s = shp + k * VC + v * 3;
            acc[3+k*3+0] += s[0] * w;
            acc[3+k*3+1] += s[1] * w;
            acc[3+k*3+2] += s[2] * w;
        }
    }
    #pragma unroll
    for (int m = 16; m > 0; m >>= 1)
        #pragma unroll
        for (int i = 0; i < 33; ++i)
            acc[i] += __shfl_xor_sync(0xffffffffu, acc[i], m);

    __shared__ float s[4][33];
    int wid = threadIdx.x >> 5, lane = threadIdx.x & 31;
    if (lane == 0)
        #pragma unroll
        for (int i = 0; i < 33; ++i) s[wid][i] = acc[i];
    __syncthreads();
    if (threadIdx.x < 33) {
        float t = s[0][threadIdx.x] + s[1][threadIdx.x] + s[2][threadIdx.x] + s[3][threadIdx.x];
        g_jmp[(j*8 + part)*33 + threadIdx.x] = t;
    }
}

__global__ void k_jmred()
{
    int i = blockIdx.x * blockDim.x + threadIdx.x;
    if (i < NJ * 33) {
        int jj = i / 33, r = i % 33;
        float t = 0.f;
        #pragma unroll
        for (int p = 0; p < 8; ++p) t += g_jmp[(jj*8 + p)*33 + r];
        g_jm[i] = t;
    }
}

// ---------------------------------------------------------------------------
// Kernel 1: fused Rodrigues + kinematic chain. 32 batches per block.
// pose-feature written COALESCED from sR after the sync (sR - I), instead of
// 9 scattered 2KB-stride stores per (b,j) in the Rodrigues loop.
// ---------------------------------------------------------------------------
__global__ void __launch_bounds__(96) k_rotchain(const float* __restrict__ inp,
                                                 float* __restrict__ out)
{
    const int PAR[NJ] = {0,0,0,0,1,2,3,4,5,6,7,8,9,9,9,12,13,14,16,17,18,19,20,21};
    __shared__ float s_jm[NJ * 33];
    __shared__ float sJ[32][NJ*3];
    __shared__ float sR[32][NJ*9];
    __shared__ float s_beta[32*NBETA];

    const int tid = threadIdx.x;
    const int b0 = blockIdx.x * 32;

    for (int i = tid; i < NJ*33; i += 96) s_jm[i] = g_jm[i];
    for (int i = tid; i < 32*NBETA; i += 96) {
        int bl = i / NBETA, k = i % NBETA;
        s_beta[i] = inp[(b0+bl)*82 + 72 + k];
    }

    for (int i = tid; i < 32*NJ; i += 96) {
        int bl = i / NJ, j = i % NJ;
        int b = b0 + bl;
        float rx = inp[b*82 + j*3 + 0];
        float ry = inp[b*82 + j*3 + 1];
        float rz = inp[b*82 + j*3 + 2];
        float ax = rx + 1e-8f, ay = ry + 1e-8f, az = rz + 1e-8f;
        float ang = sqrtf(ax*ax + ay*ay + az*az);
        float inv = 1.0f / ang;
        float nx = rx * inv, ny = ry * inv, nz = rz * inv;
        float c = cosf(ang), sn = sinf(ang), ic = 1.0f - c;
        float R[9];
        R[0] = c + ic*nx*nx;     R[1] = ic*nx*ny - sn*nz; R[2] = ic*nx*nz + sn*ny;
        R[3] = ic*ny*nx + sn*nz; R[4] = c + ic*ny*ny;     R[5] = ic*ny*nz - sn*nx;
        R[6] = ic*nz*nx - sn*ny; R[7] = ic*nz*ny + sn*nx; R[8] = c + ic*nz*nz;

        float* ro = out + ROT_OFF + (size_t)b*(NJ*9) + j*9;
        #pragma unroll
        for (int e = 0; e < 9; ++e) { ro[e] = R[e]; sR[bl][j*9+e] = R[e]; }
    }
    __syncthreads();

    // coalesced pose-feature export: row k = (j-1)*9+e across 32 batches
    for (int i = tid; i < NP*32; i += 96) {
        int bl = i & 31, krow = i >> 5;
        int j = krow / 9 + 1, e = krow % 9;
        float v = sR[bl][j*9 + e] - ((e==0||e==4||e==8) ? 1.0f : 0.0f);
        g_pfT[krow*BB + b0 + bl] = tf32r(v);
    }
    // beta rows + zero pad, coalesced
    for (int i = tid; i < (KPAD-NP)*32; i += 96) {
        int bl = i & 31, kr = NP + (i >> 5);
        float v = 0.f;
        if (kr < KTOT) v = tf32r(s_beta[bl*NBETA + (kr - NP)]);
        g_pfT[kr*BB + b0 + bl] = v;
    }

    for (int i = tid; i < 32*NJ*3; i += 96) {
        int bl = i / 72, rem = i % 72;
        int j = rem / 3, c = rem % 3;
        float t = s_jm[j*33 + c];
        #pragma unroll
        for (int k = 0; k < NBETA; ++k)
            t = fmaf(s_beta[bl*NBETA + k], s_jm[j*33 + 3 + k*3 + c], t);
        sJ[bl][j*3 + c] = t;
    }
    __syncthreads();

    const int bl = tid / 3;
    const int r  = tid % 3;
    const int b  = b0 + bl;
    const float* Rb = sR[bl];

    float row[NJ][3];
    float tw[NJ];
    row[0][0] = Rb[r*3+0]; row[0][1] = Rb[r*3+1]; row[0][2] = Rb[r*3+2];
    tw[0] = sJ[bl][r];

    #pragma unroll
    for (int j = 1; j < NJ; ++j) {
        const int p = PAR[j];
        float t0 = sJ[bl][j*3+0] - sJ[bl][p*3+0];
        float t1 = sJ[bl][j*3+1] - sJ[bl][p*3+1];
        float t2 = sJ[bl][j*3+2] - sJ[bl][p*3+2];
        float p0 = row[p][0], p1 = row[p][1], p2 = row[p][2];
        row[j][0] = p0*Rb[j*9+0] + p1*Rb[j*9+3] + p2*Rb[j*9+6];
        row[j][1] = p0*Rb[j*9+1] + p1*Rb[j*9+4] + p2*Rb[j*9+7];
        row[j][2] = p0*Rb[j*9+2] + p1*Rb[j*9+5] + p2*Rb[j*9+8];
        tw[j] = p0*t0 + p1*t1 + p2*t2 + tw[p];
    }

    float* Ao = g_A + (size_t)b * (NJ*12);
    #pragma unroll
    for (int j = 0; j < NJ; ++j) {
        float tp = tw[j] - (row[j][0]*sJ[bl][j*3+0] + row[j][1]*sJ[bl][j*3+1] + row[j][2]*sJ[bl][j*3+2]);
        float4 st = make_float4(row[j][0], row[j][1], row[j][2], tp);
        *reinterpret_cast<float4*>(&Ao[j*12 + r*4]) = st;
    }
}

// ---------------------------------------------------------------------------
// Kernel 2: blendshape GEMM (mma.sync tf32) + LBS skinning epilogue.
// (round-9/10 proven config) Tile: 128 batches x 96 cols, 256 threads.
// KS=32, d double-buffered via cp.async, pf single buffer + register staging.
// ---------------------------------------------------------------------------
__global__ void __launch_bounds__(256, 2) k_main(const float* __restrict__ lbs,
                                                 const float* __restrict__ vtempl,
                                                 float* __restrict__ out)
{
    __shared__ __align__(16) float smem[11904];
    float* s_d  = smem;            // 2 x 3328
    float* s_pf = smem + 6656;     // 32 x 136
    float* s_A  = smem;            // epilogue alias
    float* s_vp = smem + 4608;     // epilogue alias
    float* s_w  = smem + 11008;    // [32][25]
    float* s_vt = smem + 11808;    // [96]

    const int b0   = blockIdx.y * 128;
    const int col0 = blockIdx.x * 96;
    const int v0   = blockIdx.x * 32;
    const int tid  = threadIdx.x;
    const int lane = tid & 31;
    const int warp = tid >> 5;        // warp_m: 16 batches each
    const int g  = lane >> 2;         // 0..7
    const int tg = lane & 3;          // 0..3

    const unsigned sd_base = (unsigned)__cvta_generic_to_shared(s_d);

    auto load_d = [&](int kt, int buf) {
        #pragma unroll
        for (int it = 0; it < 3; ++it) {
            int i = tid + it*256;          // 0..767
            int k = i / 24, q = i % 24;
            cp_async16(sd_base + (unsigned)(buf*3328 + k*104 + q*4)*4u,
                       g_pd + (size_t)(kt*32 + k)*VCP + col0 + q*4);
        }
        cp_commit();
    };

    // initial pf tile (kt=0) straight to smem
    #pragma unroll
    for (int r = 0; r < 4; ++r) {
        int c = tid + r*256;
        int k = c >> 5, q = c & 31;
        float4 v = *reinterpret_cast<const float4*>(&g_pfT[k*BB + b0 + q*4]);
        *reinterpret_cast<float4*>(&s_pf[k*136 + q*4]) = v;
    }
    load_d(0, 0);

    float c[12][4];
    #pragma unroll
    for (int i = 0; i < 12; ++i)
        #pragma unroll
        for (int e = 0; e < 4; ++e) c[i][e] = 0.f;

    for (int kt = 0; kt < 7; ++kt) {
        const int buf = kt & 1;
        uint4 rpf[2];
        int rk[2], rq[2];
        if (kt < 6) {
            load_d(kt+1, buf ^ 1);
            #pragma unroll
            for (int r = 0; r < 2; ++r) {
                int cc = tid + r*256;
                rk[r] = cc >> 5; rq[r] = cc & 31;
                rpf[r] = *reinterpret_cast<const uint4*>(
                    &g_pfT[((kt+1)*32 + rk[r])*BB + b0 + rq[r]*4]);
            }
        }
        if (kt < 6) cp_wait<1>(); else cp_wait<0>();
        __syncthreads();

        const float*    pa = s_pf + tg*136 + warp*16 + g;
        const unsigned* pb = reinterpret_cast<const unsigned*>(s_d + buf*3328) + tg*104 + g;

        #pragma unroll
        for (int ks = 0; ks < 4; ++ks) {
            const float*    pak = pa + ks*1088;   // ks*8*136
            const unsigned* pbk = pb + ks*832;    // ks*8*104
            unsigned a[4];
            a[0] = __float_as_uint(pak[0]);
            a[1] = __float_as_uint(pak[8]);
            a[2] = __float_as_uint(pak[544]);     // +4*136
            a[3] = __float_as_uint(pak[552]);
            #pragma unroll
            for (int nt = 0; nt < 12; ++nt) {
                unsigned bb0 = pbk[nt*8];
                unsigned bb1 = pbk[nt*8 + 416];   // +4*104
                mma_tf32(c[nt], a, bb0, bb1);
            }
        }
        __syncthreads();

        if (kt < 6) {
            #pragma unroll
            for (int r = 0; r < 2; ++r)
                *reinterpret_cast<uint4*>(&s_pf[rk[r]*136 + rq[r]*4]) = rpf[r];
            #pragma unroll
            for (int r = 2; r < 4; ++r) {
                int cc = tid + r*256;
                int k = cc >> 5, q = cc & 31;
                float4 v = *reinterpret_cast<const float4*>(
                    &g_pfT[((kt+1)*32 + k)*BB + b0 + q*4]);
                *reinterpret_cast<float4*>(&s_pf[k*136 + q*4]) = v;
            }
        }
    }

    // ---- epilogue: LBS skinning ----
    for (int i = tid; i < 768; i += 256) {
        int vl = i / 24, j = i % 24;
        int v = v0 + vl;
        s_w[vl*25 + j] = (v < VV) ? lbs[(size_t)v*NJ + j] : 0.f;
    }
    if (tid < 96) {
        int cg = col0 + tid;
        s_vt[tid] = (cg < VC) ? vtempl[cg] : 0.f;
    }

    const u64 z2 = pack2(0.f, 0.f);
    const int tv = tid & 15;
    const int tb = tid >> 4;
    const int vg0 = v0 + tv*2;
    const int vg1 = vg0 + 1;

    #pragma unroll
    for (int pass = 0; pass < 8; ++pass) {
        __syncthreads();
        if (warp == pass) {
            #pragma unroll
            for (int nt = 0; nt < 12; ++nt) {
                int colL = nt*8 + tg*2;
                float vt0 = s_vt[colL], vt1 = s_vt[colL+1];
                s_vp[g*96 + colL]        = c[nt][0] + vt0;
                s_vp[g*96 + colL + 1]    = c[nt][1] + vt1;
                s_vp[(g+8)*96 + colL]    = c[nt][2] + vt0;
                s_vp[(g+8)*96 + colL+1]  = c[nt][3] + vt1;
            }
        }
        {
            const float4* gA4 = reinterpret_cast<const float4*>(g_A + (size_t)(b0 + pass*16)*288);
            #pragma unroll
            for (int i = 0; i < 5; ++i) {
                int idx = tid + i*256;
                if (idx < 1152) reinterpret_cast<float4*>(s_A)[idx] = gA4[idx];
            }
        }
        __syncthreads();

        const int b = b0 + pass*16 + tb;
        const ulonglong2* Ar2 = reinterpret_cast<const ulonglong2*>(s_A + tb*288);
        u64 T0[6], T1[6];
        #pragma unroll
        for (int i = 0; i < 6; ++i) { T0[i] = z2; T1[i] = z2; }
        #pragma unroll
        for (int j = 0; j < NJ; ++j) {
            ulonglong2 A01 = Ar2[j*3 + 0];
            ulonglong2 A23 = Ar2[j*3 + 1];
            ulonglong2 A45 = Ar2[j*3 + 2];
            float w0 = s_w[(tv*2 + 0)*25 + j];
            float w1 = s_w[(tv*2 + 1)*25 + j];
            u64 w0d = pack2(w0, w0);
            u64 w1d = pack2(w1, w1);
            T0[0] = ffma2(w0d, A01.x, T0[0]); T0[1] = ffma2(w0d, A01.y, T0[1]);
            T0[2] = ffma2(w0d, A23.x, T0[2]); T0[3] = ffma2(w0d, A23.y, T0[3]);
            T0[4] = ffma2(w0d, A45.x, T0[4]); T0[5] = ffma2(w0d, A45.y, T0[5]);
            T1[0] = ffma2(w1d, A01.x, T1[0]); T1[1] = ffma2(w1d, A01.y, T1[1]);
            T1[2] = ffma2(w1d, A23.x, T1[2]); T1[3] = ffma2(w1d, A23.y, T1[3]);
            T1[4] = ffma2(w1d, A45.x, T1[4]); T1[5] = ffma2(w1d, A45.y, T1[5]);
        }
        if (vg0 < VV) {
            float x = s_vp[tb*96 + tv*6 + 0];
            float y = s_vp[tb*96 + tv*6 + 1];
            float z = s_vp[tb*96 + tv*6 + 2];
            float2 r0 = unpack2(T0[0]), r1 = unpack2(T0[1]);
            float2 r2 = unpack2(T0[2]), r3 = unpack2(T0[3]);
            float2 r4 = unpack2(T0[4]), r5 = unpack2(T0[5]);
            float* o = out + (size_t)b*VC + vg0*3;
            o[0] = r0.x*x + r0.y*y + r1.x*z + r1.y;
            o[1] = r2.x*x + r2.y*y + r3.x*z + r3.y;
            o[2] = r4.x*x + r4.y*y + r5.x*z + r5.y;
        }
        if (vg1 < VV) {
            float x = s_vp[tb*96 + tv*6 + 3];
            float y = s_vp[tb*96 + tv*6 + 4];
            float z = s_vp[tb*96 + tv*6 + 5];
            float2 r0 = unpack2(T1[0]), r1 = unpack2(T1[1]);
            float2 r2 = unpack2(T1[2]), r3 = unpack2(T1[3]);
            float2 r4 = unpack2(T1[4]), r5 = unpack2(T1[5]);
            float* o = out + (size_t)b*VC + vg1*3;
            o[0] = r0.x*x + r0.y*y + r1.x*z + r1.y;
            o[1] = r2.x*x + r2.y*y + r3.x*z + r3.y;
            o[2] = r4.x*x + r4.y*y + r5.x*z + r5.y;
        }
    }
}

// ---------------------------------------------------------------------------
// Kernel 3: joints = vertices @ joint_regressor (deterministic 2-stage).
// jreg j-pairs pre-packed as u64 in smem [jp][512]; FFMA2 accumulation.
// ---------------------------------------------------------------------------
__global__ void __launch_bounds__(256) k_jnt_part(const float* __restrict__ outv,
                                                  const float* __restrict__ jreg)
{
    __shared__ u64 s_jp[10 * 512];   // 40 KB
    const int chunk = blockIdx.x;
    const int v0 = chunk * 512;
    for (int i = threadIdx.x; i < 10*512; i += 256) {
        int jp = i >> 9, vl = i & 511;
        int vg = v0 + vl;
        float r0 = 0.f, r1 = 0.f;
        if (vg < VV) {
            r0 = jreg[vg*NJO + 2*jp];
            if (2*jp + 1 < NJO) r1 = jreg[vg*NJO + 2*jp + 1];
        }
        s_jp[jp*512 + vl] = pack2(r0, r1);
    }
    __syncthreads();

    const int bl = threadIdx.x >> 5, lane = threadIdx.x & 31;
    const int b = blockIdx.y * 8 + bl;

    u64 ax[10], ay[10], az[10];
    const u64 z2 = pack2(0.f, 0.f);
    #pragma unroll
    for (int i = 0; i < 10; ++i) { ax[i] = z2; ay[i] = z2; az[i] = z2; }

    #pragma unroll 4
    for (int i = 0; i < 16; ++i) {
        int vl = lane + i*32;
        int vg = v0 + vl;
        if (vg < VV) {
            const float* p = outv + (size_t)b*VC + vg*3;
            float x = p[0], y = p[1], z = p[2];
            u64 xx = pack2(x, x), yy = pack2(y, y), zz = pack2(z, z);
            #pragma unroll
            for (int jp = 0; jp < 10; ++jp) {
                u64 rp = s_jp[jp*512 + vl];
                ax[jp] = ffma2(rp, xx, ax[jp]);
                ay[jp] = ffma2(rp, yy, ay[jp]);
                az[jp] = ffma2(rp, zz, az[jp]);
            }
        }
    }
    #pragma unroll
    for (int m = 16; m > 0; m >>= 1)
        #pragma unroll
        for (int jp = 0; jp < 10; ++jp) {
            ax[jp] = add2(ax[jp], __shfl_xor_sync(0xffffffffu, ax[jp], m));
            ay[jp] = add2(ay[jp], __shfl_xor_sync(0xffffffffu, ay[jp], m));
            az[jp] = add2(az[jp], __shfl_xor_sync(0xffffffffu, az[jp], m));
        }

    if (lane == 0) {
        float* dst = g_jpart + (size_t)(b*14 + chunk)*57;
        #pragma unroll
        for (int jp = 0; jp < 10; ++jp) {
            float2 fx = unpack2(ax[jp]);
            float2 fy = unpack2(ay[jp]);
            float2 fz = unpack2(az[jp]);
            int j0 = 2*jp;
            dst[j0*3+0] = fx.x; dst[j0*3+1] = fy.x; dst[j0*3+2] = fz.x;
            if (j0 + 1 < NJO) {
                dst[(j0+1)*3+0] = fx.y; dst[(j0+1)*3+1] = fy.y; dst[(j0+1)*3+2] = fz.y;
            }
        }
    }
}

__global__ void k_jnt_red(float* __restrict__ out)
{
    int i = blockIdx.x * blockDim.x + threadIdx.x;
    if (i < BB * 57) {
        int b = i / 57, r = i % 57;
        float t = 0.f;
        #pragma unroll
        for (int p = 0; p < 14; ++p) t += g_jpart[(size_t)(b*14 + p)*57 + r];
        out[JNT_OFF + i] = t;
    }
}

// ---------------------------------------------------------------------------
extern "C" void kernel_launch(void* const* d_in, const int* in_sizes, int n_in,
                              void* d_out, int out_size)
{
    const float* inputs   = (const float*)d_in[0];
    const float* v_templ  = (const float*)d_in[1];
    const float* shapes   = (const float*)d_in[2];
    const float* posedirs = (const float*)d_in[3];
    const float* smpl_reg = (const float*)d_in[4];
    const float* lbs_w    = (const float*)d_in[5];
    const float* joint_rg = (const float*)d_in[6];
    float* out = (float*)d_out;

    k_round<<<dim3(21, KPAD), 256>>>(posedirs, shapes);

    k_jm<<<dim3(NJ, 8), 128>>>(v_templ, shapes, smpl_reg);
    k_jmred<<<4, 256>>>();

    k_rotchain<<<16, 96>>>(inputs, out);

    k_main<<<dim3(216, 4), 256>>>(lbs_w, v_templ, out);

    k_jnt_part<<<dim3(14, 64), 256>>>(out, joint_rg);
    k_jnt_red<<<(BB*57 + 255)/256, 256>>>(out);
}

// round 15
// speedup vs baseline: 1.1829x; 1.1469x over previous
#include <cuda_runtime.h>
#include <cuda_bf16.h>
#include <math.h>

// ---------------------------------------------------------------------------
#define BB 512
#define VV 6890
#define NJ 24
#define NBETA 10
#define NP 207
#define NJO 19
#define VC (VV*3)              // 20670
#define VCP 20736              // padded cols (216*96)
#define KTOT 217
#define KPAD 224               // 7*32
#define JNT_OFF  (BB*VC)
#define ROT_OFF  (JNT_OFF + BB*NJO*3)

typedef unsigned long long u64;

__device__ __forceinline__ u64 ffma2(u64 a, u64 b, u64 c) {
    u64 d;
    asm("fma.rn.f32x2 %0, %1, %2, %3;" : "=l"(d) : "l"(a), "l"(b), "l"(c));
    return d;
}
__device__ __forceinline__ u64 pack2(float lo, float hi) {
    u64 d;
    asm("mov.b64 %0, {%1, %2};" : "=l"(d) : "f"(lo), "f"(hi));
    return d;
}
__device__ __forceinline__ float2 unpack2(u64 v) {
    float2 f;
    asm("mov.b64 {%0, %1}, %2;" : "=f"(f.x), "=f"(f.y) : "l"(v));
    return f;
}
__device__ __forceinline__ void cp_async16(unsigned saddr, const void* gaddr) {
    asm volatile("cp.async.ca.shared.global [%0], [%1], 16;"
                 :: "r"(saddr), "l"(gaddr));
}
__device__ __forceinline__ void cp_commit() {
    asm volatile("cp.async.commit_group;");
}
template<int N>
__device__ __forceinline__ void cp_wait() {
    asm volatile("cp.async.wait_group %0;" :: "n"(N));
}
__device__ __forceinline__ float tf32r(float x) {
    unsigned u;
    asm("cvt.rna.tf32.f32 %0, %1;" : "=r"(u) : "f"(x));
    return __uint_as_float(u);
}
__device__ __forceinline__ unsigned tf32u(float x) {
    unsigned u;
    asm("cvt.rna.tf32.f32 %0, %1;" : "=r"(u) : "f"(x));
    return u;
}
__device__ __forceinline__ void mma_tf32(float* c, const unsigned* a, unsigned b0, unsigned b1) {
    asm("mma.sync.aligned.m16n8k8.row.col.f32.tf32.tf32.f32 "
        "{%0,%1,%2,%3},{%4,%5,%6,%7},{%8,%9},{%0,%1,%2,%3};"
        : "+f"(c[0]), "+f"(c[1]), "+f"(c[2]), "+f"(c[3])
        : "r"(a[0]), "r"(a[1]), "r"(a[2]), "r"(a[3]), "r"(b0), "r"(b1));
}

// ---------------------------------------------------------------------------
__device__ float    g_pfT[KPAD * BB];
__device__ unsigned g_pd[(size_t)KPAD * VCP];
__device__ float    g_A[BB * NJ * 12];
__device__ float    g_jmp[NJ * 8 * 33];
__device__ float    g_jpart[BB * 14 * 57];

// ---------------------------------------------------------------------------
// Kernel PRE: fused (a) tf32 pre-round of [posedirs;shapes] -> g_pd and
// (b) rest-joint regressor partials -> g_jmp. Independent work, one launch.
// Blocks [0, 4704): round part. Blocks [4704, 4896): jm part (24 j x 8 chunks).
// ---------------------------------------------------------------------------
__global__ void __launch_bounds__(256) k_pre(const float* __restrict__ pd,
                                             const float* __restrict__ sh,
                                             const float* __restrict__ vt,
                                             const float* __restrict__ sr)
{
    const int bx = blockIdx.x;
    if (bx < 4704) {
        int k  = bx / 21;
        int cb = bx % 21;
        int c4 = (cb * 256 + threadIdx.x) * 4;
        if (c4 >= VCP) return;
        uint4 o;
        #pragma unroll
        for (int e = 0; e < 4; ++e) {
            int c = c4 + e;
            float f = 0.f;
            if (c < VC) {
                if (k < NP)        f = pd[(size_t)k*VC + c];
                else if (k < KTOT) f = sh[(size_t)(k-NP)*VC + c];
            }
            (&o.x)[e] = tf32u(f);
        }
        *reinterpret_cast<uint4*>(&g_pd[(size_t)k*VCP + c4]) = o;
        return;
    }

    // ---- jm part: 256 threads ----
    const int idx = bx - 4704;
    const int j = idx >> 3, part = idx & 7;
    int vs = part * 862;
    int ve = vs + 862; if (ve > VV) ve = VV;

    float acc[33];
    #pragma unroll
    for (int i = 0; i < 33; ++i) acc[i] = 0.f;

    for (int v = vs + threadIdx.x; v < ve; v += 256) {
        float w = sr[v * NJ + j];
        acc[0] += vt[v*3+0] * w;
        acc[1] += vt[v*3+1] * w;
        acc[2] += vt[v*3+2] * w;
        #pragma unroll
        for (int k = 0; k < NBETA; ++k) {
            const float* s = sh + k * VC + v * 3;
            acc[3+k*3+0] += s[0] * w;
            acc[3+k*3+1] += s[1] * w;
            acc[3+k*3+2] += s[2] * w;
        }
    }
    #pragma unroll
    for (int m = 16; m > 0; m >>= 1)
        #pragma unroll
        for (int i = 0; i < 33; ++i)
            acc[i] += __shfl_xor_sync(0xffffffffu, acc[i], m);

    __shared__ float s[8][33];
    int wid = threadIdx.x >> 5, lane = threadIdx.x & 31;
    if (lane == 0)
        #pragma unroll
        for (int i = 0; i < 33; ++i) s[wid][i] = acc[i];
    __syncthreads();
    if (threadIdx.x < 33) {
        float t = 0.f;
        #pragma unroll
        for (int w = 0; w < 8; ++w) t += s[w][threadIdx.x];
        g_jmp[(j*8 + part)*33 + threadIdx.x] = t;
    }
}

// ---------------------------------------------------------------------------
// Kernel 1: fused jmp-reduce + Rodrigues + kinematic chain.
// 8 batches per block (grid 64) for 4x more SM parallelism on the
// latency-bound phases.
// ---------------------------------------------------------------------------
__global__ void __launch_bounds__(96) k_rotchain(const float* __restrict__ inp,
                                                 float* __restrict__ out)
{
    const int PAR[NJ] = {0,0,0,0,1,2,3,4,5,6,7,8,9,9,9,12,13,14,16,17,18,19,20,21};
    __shared__ float s_jm[NJ * 33];
    __shared__ float sJ[8][NJ*3];
    __shared__ float sR[8][NJ*9];
    __shared__ float s_beta[8*NBETA];

    const int tid = threadIdx.x;
    const int b0 = blockIdx.x * 8;

    // inline jmred: reduce 8 partials per (j, r)
    for (int i = tid; i < NJ*33; i += 96) {
        int j = i / 33, r = i % 33;
        float t = 0.f;
        #pragma unroll
        for (int p = 0; p < 8; ++p) t += g_jmp[(j*8 + p)*33 + r];
        s_jm[i] = t;
    }
    for (int i = tid; i < 8*NBETA; i += 96) {
        int bl = i / NBETA, k = i % NBETA;
        s_beta[i] = inp[(b0+bl)*82 + 72 + k];
    }

    // Rodrigues: 192 items, 2 per thread
    for (int i = tid; i < 8*NJ; i += 96) {
        int bl = i / NJ, j = i % NJ;
        int b = b0 + bl;
        float rx = inp[b*82 + j*3 + 0];
        float ry = inp[b*82 + j*3 + 1];
        float rz = inp[b*82 + j*3 + 2];
        float ax = rx + 1e-8f, ay = ry + 1e-8f, az = rz + 1e-8f;
        float ang = sqrtf(ax*ax + ay*ay + az*az);
        float inv = 1.0f / ang;
        float nx = rx * inv, ny = ry * inv, nz = rz * inv;
        float c = cosf(ang), sn = sinf(ang), ic = 1.0f - c;
        float R[9];
        R[0] = c + ic*nx*nx;     R[1] = ic*nx*ny - sn*nz; R[2] = ic*nx*nz + sn*ny;
        R[3] = ic*ny*nx + sn*nz; R[4] = c + ic*ny*ny;     R[5] = ic*ny*nz - sn*nx;
        R[6] = ic*nz*nx - sn*ny; R[7] = ic*nz*ny + sn*nx; R[8] = c + ic*nz*nz;

        float* ro = out + ROT_OFF + (size_t)b*(NJ*9) + j*9;
        #pragma unroll
        for (int e = 0; e < 9; ++e) { ro[e] = R[e]; sR[bl][j*9+e] = R[e]; }
    }
    __syncthreads();

    // pose-feature export: row k = (j-1)*9+e across 8 batches
    for (int i = tid; i < NP*8; i += 96) {
        int bl = i & 7, krow = i >> 3;
        int j = krow / 9 + 1, e = krow % 9;
        float v = sR[bl][j*9 + e] - ((e==0||e==4||e==8) ? 1.0f : 0.0f);
        g_pfT[krow*BB + b0 + bl] = tf32r(v);
    }
    // beta rows + zero pad
    for (int i = tid; i < (KPAD-NP)*8; i += 96) {
        int bl = i & 7, kr = NP + (i >> 3);
        float v = 0.f;
        if (kr < KTOT) v = tf32r(s_beta[bl*NBETA + (kr - NP)]);
        g_pfT[kr*BB + b0 + bl] = v;
    }

    // rest joints
    for (int i = tid; i < 8*NJ*3; i += 96) {
        int bl = i / 72, rem = i % 72;
        int j = rem / 3, c = rem % 3;
        float t = s_jm[j*33 + c];
        #pragma unroll
        for (int k = 0; k < NBETA; ++k)
            t = fmaf(s_beta[bl*NBETA + k], s_jm[j*33 + 3 + k*3 + c], t);
        sJ[bl][j*3 + c] = t;
    }
    __syncthreads();

    // kinematic chain: one thread per (batch, affine-row) = 24 threads
    if (tid < 24) {
        const int bl = tid / 3;
        const int r  = tid % 3;
        const int b  = b0 + bl;
        const float* Rb = sR[bl];

        float row[NJ][3];
        float tw[NJ];
        row[0][0] = Rb[r*3+0]; row[0][1] = Rb[r*3+1]; row[0][2] = Rb[r*3+2];
        tw[0] = sJ[bl][r];

        #pragma unroll
        for (int j = 1; j < NJ; ++j) {
            const int p = PAR[j];
            float t0 = sJ[bl][j*3+0] - sJ[bl][p*3+0];
            float t1 = sJ[bl][j*3+1] - sJ[bl][p*3+1];
            float t2 = sJ[bl][j*3+2] - sJ[bl][p*3+2];
            float p0 = row[p][0], p1 = row[p][1], p2 = row[p][2];
            row[j][0] = p0*Rb[j*9+0] + p1*Rb[j*9+3] + p2*Rb[j*9+6];
            row[j][1] = p0*Rb[j*9+1] + p1*Rb[j*9+4] + p2*Rb[j*9+7];
            row[j][2] = p0*Rb[j*9+2] + p1*Rb[j*9+5] + p2*Rb[j*9+8];
            tw[j] = p0*t0 + p1*t1 + p2*t2 + tw[p];
        }

        float* Ao = g_A + (size_t)b * (NJ*12);
        #pragma unroll
        for (int j = 0; j < NJ; ++j) {
            float tp = tw[j] - (row[j][0]*sJ[bl][j*3+0] + row[j][1]*sJ[bl][j*3+1] + row[j][2]*sJ[bl][j*3+2]);
            float4 st = make_float4(row[j][0], row[j][1], row[j][2], tp);
            *reinterpret_cast<float4*>(&Ao[j*12 + r*4]) = st;
        }
    }
}

// ---------------------------------------------------------------------------
// Kernel 2: blendshape GEMM (mma.sync tf32) + LBS skinning epilogue.
// (round-10 proven config, unchanged) Tile: 128 batches x 96 cols, 256 threads.
// ---------------------------------------------------------------------------
__global__ void __launch_bounds__(256, 2) k_main(const float* __restrict__ lbs,
                                                 const float* __restrict__ vtempl,
                                                 float* __restrict__ out)
{
    __shared__ __align__(16) float smem[11904];
    float* s_d  = smem;            // 2 x 3328
    float* s_pf = smem + 6656;     // 32 x 136
    float* s_A  = smem;            // epilogue alias
    float* s_vp = smem + 4608;     // epilogue alias
    float* s_w  = smem + 11008;    // [32][25]
    float* s_vt = smem + 11808;    // [96]

    const int b0   = blockIdx.y * 128;
    const int col0 = blockIdx.x * 96;
    const int v0   = blockIdx.x * 32;
    const int tid  = threadIdx.x;
    const int lane = tid & 31;
    const int warp = tid >> 5;
    const int g  = lane >> 2;
    const int tg = lane & 3;

    const unsigned sd_base = (unsigned)__cvta_generic_to_shared(s_d);

    auto load_d = [&](int kt, int buf) {
        #pragma unroll
        for (int it = 0; it < 3; ++it) {
            int i = tid + it*256;
            int k = i / 24, q = i % 24;
            cp_async16(sd_base + (unsigned)(buf*3328 + k*104 + q*4)*4u,
                       g_pd + (size_t)(kt*32 + k)*VCP + col0 + q*4);
        }
        cp_commit();
    };

    #pragma unroll
    for (int r = 0; r < 4; ++r) {
        int c = tid + r*256;
        int k = c >> 5, q = c & 31;
        float4 v = *reinterpret_cast<const float4*>(&g_pfT[k*BB + b0 + q*4]);
        *reinterpret_cast<float4*>(&s_pf[k*136 + q*4]) = v;
    }
    load_d(0, 0);

    float c[12][4];
    #pragma unroll
    for (int i = 0; i < 12; ++i)
        #pragma unroll
        for (int e = 0; e < 4; ++e) c[i][e] = 0.f;

    for (int kt = 0; kt < 7; ++kt) {
        const int buf = kt & 1;
        uint4 rpf[2];
        int rk[2], rq[2];
        if (kt < 6) {
            load_d(kt+1, buf ^ 1);
            #pragma unroll
            for (int r = 0; r < 2; ++r) {
                int cc = tid + r*256;
                rk[r] = cc >> 5; rq[r] = cc & 31;
                rpf[r] = *reinterpret_cast<const uint4*>(
                    &g_pfT[((kt+1)*32 + rk[r])*BB + b0 + rq[r]*4]);
            }
        }
        if (kt < 6) cp_wait<1>(); else cp_wait<0>();
        __syncthreads();

        const float*    pa = s_pf + tg*136 + warp*16 + g;
        const unsigned* pb = reinterpret_cast<const unsigned*>(s_d + buf*3328) + tg*104 + g;

        #pragma unroll
        for (int ks = 0; ks < 4; ++ks) {
            const float*    pak = pa + ks*1088;
            const unsigned* pbk = pb + ks*832;
            unsigned a[4];
            a[0] = __float_as_uint(pak[0]);
            a[1] = __float_as_uint(pak[8]);
            a[2] = __float_as_uint(pak[544]);
            a[3] = __float_as_uint(pak[552]);
            #pragma unroll
            for (int nt = 0; nt < 12; ++nt) {
                unsigned bb0 = pbk[nt*8];
                unsigned bb1 = pbk[nt*8 + 416];
                mma_tf32(c[nt], a, bb0, bb1);
            }
        }
        __syncthreads();

        if (kt < 6) {
            #pragma unroll
            for (int r = 0; r < 2; ++r)
                *reinterpret_cast<uint4*>(&s_pf[rk[r]*136 + rq[r]*4]) = rpf[r];
            #pragma unroll
            for (int r = 2; r < 4; ++r) {
                int cc = tid + r*256;
                int k = cc >> 5, q = cc & 31;
                float4 v = *reinterpret_cast<const float4*>(
                    &g_pfT[((kt+1)*32 + k)*BB + b0 + q*4]);
                *reinterpret_cast<float4*>(&s_pf[k*136 + q*4]) = v;
            }
        }
    }

    // ---- epilogue: LBS skinning ----
    for (int i = tid; i < 768; i += 256) {
        int vl = i / 24, j = i % 24;
        int v = v0 + vl;
        s_w[vl*25 + j] = (v < VV) ? lbs[(size_t)v*NJ + j] : 0.f;
    }
    if (tid < 96) {
        int cg = col0 + tid;
        s_vt[tid] = (cg < VC) ? vtempl[cg] : 0.f;
    }

    const u64 z2 = pack2(0.f, 0.f);
    const int tv = tid & 15;
    const int tb = tid >> 4;
    const int vg0 = v0 + tv*2;
    const int vg1 = vg0 + 1;

    #pragma unroll
    for (int pass = 0; pass < 8; ++pass) {
        __syncthreads();
        if (warp == pass) {
            #pragma unroll
            for (int nt = 0; nt < 12; ++nt) {
                int colL = nt*8 + tg*2;
                float vt0 = s_vt[colL], vt1 = s_vt[colL+1];
                s_vp[g*96 + colL]        = c[nt][0] + vt0;
                s_vp[g*96 + colL + 1]    = c[nt][1] + vt1;
                s_vp[(g+8)*96 + colL]    = c[nt][2] + vt0;
                s_vp[(g+8)*96 + colL+1]  = c[nt][3] + vt1;
            }
        }
        {
            const float4* gA4 = reinterpret_cast<const float4*>(g_A + (size_t)(b0 + pass*16)*288);
            #pragma unroll
            for (int i = 0; i < 5; ++i) {
                int idx = tid + i*256;
                if (idx < 1152) reinterpret_cast<float4*>(s_A)[idx] = gA4[idx];
            }
        }
        __syncthreads();

        const int b = b0 + pass*16 + tb;
        const ulonglong2* Ar2 = reinterpret_cast<const ulonglong2*>(s_A + tb*288);
        u64 T0[6], T1[6];
        #pragma unroll
        for (int i = 0; i < 6; ++i) { T0[i] = z2; T1[i] = z2; }
        #pragma unroll
        for (int j = 0; j < NJ; ++j) {
            ulonglong2 A01 = Ar2[j*3 + 0];
            ulonglong2 A23 = Ar2[j*3 + 1];
            ulonglong2 A45 = Ar2[j*3 + 2];
            float w0 = s_w[(tv*2 + 0)*25 + j];
            float w1 = s_w[(tv*2 + 1)*25 + j];
            u64 w0d = pack2(w0, w0);
            u64 w1d = pack2(w1, w1);
            T0[0] = ffma2(w0d, A01.x, T0[0]); T0[1] = ffma2(w0d, A01.y, T0[1]);
            T0[2] = ffma2(w0d, A23.x, T0[2]); T0[3] = ffma2(w0d, A23.y, T0[3]);
            T0[4] = ffma2(w0d, A45.x, T0[4]); T0[5] = ffma2(w0d, A45.y, T0[5]);
            T1[0] = ffma2(w1d, A01.x, T1[0]); T1[1] = ffma2(w1d, A01.y, T1[1]);
            T1[2] = ffma2(w1d, A23.x, T1[2]); T1[3] = ffma2(w1d, A23.y, T1[3]);
            T1[4] = ffma2(w1d, A45.x, T1[4]); T1[5] = ffma2(w1d, A45.y, T1[5]);
        }
        if (vg0 < VV) {
            float x = s_vp[tb*96 + tv*6 + 0];
            float y = s_vp[tb*96 + tv*6 + 1];
            float z = s_vp[tb*96 + tv*6 + 2];
            float2 r0 = unpack2(T0[0]), r1 = unpack2(T0[1]);
            float2 r2 = unpack2(T0[2]), r3 = unpack2(T0[3]);
            float2 r4 = unpack2(T0[4]), r5 = unpack2(T0[5]);
            float* o = out + (size_t)b*VC + vg0*3;
            o[0] = r0.x*x + r0.y*y + r1.x*z + r1.y;
            o[1] = r2.x*x + r2.y*y + r3.x*z + r3.y;
            o[2] = r4.x*x + r4.y*y + r5.x*z + r5.y;
        }
        if (vg1 < VV) {
            float x = s_vp[tb*96 + tv*6 + 3];
            float y = s_vp[tb*96 + tv*6 + 4];
            float z = s_vp[tb*96 + tv*6 + 5];
            float2 r0 = unpack2(T1[0]), r1 = unpack2(T1[1]);
            float2 r2 = unpack2(T1[2]), r3 = unpack2(T1[3]);
            float2 r4 = unpack2(T1[4]), r5 = unpack2(T1[5]);
            float* o = out + (size_t)b*VC + vg1*3;
            o[0] = r0.x*x + r0.y*y + r1.x*z + r1.y;
            o[1] = r2.x*x + r2.y*y + r3.x*z + r3.y;
            o[2] = r4.x*x + r4.y*y + r5.x*z + r5.y;
        }
    }
}

// ---------------------------------------------------------------------------
// Kernel 3: joints = vertices @ joint_regressor (round-10 proven version)
// ---------------------------------------------------------------------------
__global__ void __launch_bounds__(256) k_jnt_part(const float* __restrict__ outv,
                                                  const float* __restrict__ jreg)
{
    __shared__ float s_jr[512 * NJO];
    const int chunk = blockIdx.x;
    const int v0 = chunk * 512;
    for (int i = threadIdx.x; i < 512*NJO; i += 256) {
        int v = v0 + i / NJO;
        s_jr[i] = (v < VV) ? jreg[v*NJO + (i % NJO)] : 0.f;
    }
    __syncthreads();

    const int bl = threadIdx.x >> 5, lane = threadIdx.x & 31;
    const int b = blockIdx.y * 8 + bl;

    float acc[57];
    #pragma unroll
    for (int i = 0; i < 57; ++i) acc[i] = 0.f;

    #pragma unroll 4
    for (int i = 0; i < 16; ++i) {
        int vl = lane + i*32;
        int vg = v0 + vl;
        if (vg < VV) {
            const float* p = outv + (size_t)b*VC + vg*3;
            float x = p[0], y = p[1], z = p[2];
            #pragma unroll
            for (int j = 0; j < NJO; ++j) {
                float r = s_jr[vl*NJO + j];
                acc[j*3+0] = fmaf(r, x, acc[j*3+0]);
                acc[j*3+1] = fmaf(r, y, acc[j*3+1]);
                acc[j*3+2] = fmaf(r, z, acc[j*3+2]);
            }
        }
    }
    #pragma unroll
    for (int m = 16; m > 0; m >>= 1)
        #pragma unroll
        for (int i = 0; i < 57; ++i)
            acc[i] += __shfl_xor_sync(0xffffffffu, acc[i], m);

    if (lane == 0) {
        float* dst = g_jpart + (size_t)(b*14 + chunk)*57;
        #pragma unroll
        for (int i = 0; i < 57; ++i) dst[i] = acc[i];
    }
}

__global__ void k_jnt_red(float* __restrict__ out)
{
    int i = blockIdx.x * blockDim.x + threadIdx.x;
    if (i < BB * 57) {
        int b = i / 57, r = i % 57;
        float t = 0.f;
        #pragma unroll
        for (int p = 0; p < 14; ++p) t += g_jpart[(size_t)(b*14 + p)*57 + r];
        out[JNT_OFF + i] = t;
    }
}

// ---------------------------------------------------------------------------
extern "C" void kernel_launch(void* const* d_in, const int* in_sizes, int n_in,
                              void* d_out, int out_size)
{
    const float* inputs   = (const float*)d_in[0];
    const float* v_templ  = (const float*)d_in[1];
    const float* shapes   = (const float*)d_in[2];
    const float* posedirs = (const float*)d_in[3];
    const float* smpl_reg = (const float*)d_in[4];
    const float* lbs_w    = (const float*)d_in[5];
    const float* joint_rg = (const float*)d_in[6];
    float* out = (float*)d_out;

    // fused: tf32 pre-round (4704 blocks) + joint-regressor partials (192 blocks)
    k_pre<<<4896, 256>>>(posedirs, shapes, v_templ, smpl_reg);

    // fused: jmp reduce + Rodrigues + kinematic chain (8 batches/block)
    k_rotchain<<<64, 96>>>(inputs, out);

    k_main<<<dim3(216, 4), 256>>>(lbs_w, v_templ, out);

    k_jnt_part<<<dim3(14, 64), 256>>>(out, joint_rg);
    k_jnt_red<<<(BB*57 + 255)/256, 256>>>(out);
}